// round 2
// baseline (speedup 1.0000x reference)
#include <cuda_runtime.h>
#include <math.h>

#define SB   2048   // sequence length
#define HID  2048   // hidden dim
#define NHQ  16
#define NHKV 4
#define DH   128
#define NB   2

// ---------------- scratch (device globals; no allocation allowed) ----------------
__device__ float g_h [(size_t)NB*SB*HID];        // rmsnorm output        33.5 MB
__device__ float g_q [(size_t)NB*NHQ *SB*DH];    // q in [B,Hq,S,D]       33.5 MB
__device__ float g_k [(size_t)NB*NHKV*SB*DH];    // k in [B,Hkv,S,D]       8.4 MB
__device__ float g_v [(size_t)NB*NHKV*SB*DH];    // v in [B,Hkv,S,D]       8.4 MB
__device__ float g_ao[(size_t)NB*SB*NHQ*DH];     // attn out [B,S,HqD]    33.5 MB
__device__ float g_cos[SB*64];
__device__ float g_sin[SB*64];

// ---------------- RMSNorm ----------------
__global__ void rmsnorm_kernel(const float* __restrict__ x,
                               const float* __restrict__ w,
                               float* __restrict__ out) {
    int row = blockIdx.x;
    int t = threadIdx.x;
    const float4* xr = (const float4*)(x + (size_t)row * HID);
    float4*       op = (float4*)(out + (size_t)row * HID);
    const float4* w4 = (const float4*)w;

    float4 a = xr[t];
    float4 b = xr[t + 256];
    float ss = a.x*a.x + a.y*a.y + a.z*a.z + a.w*a.w
             + b.x*b.x + b.y*b.y + b.z*b.z + b.w*b.w;

    __shared__ float red[8];
    #pragma unroll
    for (int o = 16; o; o >>= 1) ss += __shfl_xor_sync(0xffffffffu, ss, o);
    if ((t & 31) == 0) red[t >> 5] = ss;
    __syncthreads();
    float tot = red[0]+red[1]+red[2]+red[3]+red[4]+red[5]+red[6]+red[7];
    float inv = rsqrtf(tot * (1.0f/HID) + 1e-6f);

    float4 wa = w4[t], wb = w4[t + 256];
    op[t]       = make_float4(a.x*inv*wa.x, a.y*inv*wa.y, a.z*inv*wa.z, a.w*inv*wa.w);
    op[t + 256] = make_float4(b.x*inv*wb.x, b.y*inv*wb.y, b.z*inv*wb.z, b.w*inv*wb.w);
}

// ---------------- RoPE ----------------
__global__ void rope_table_kernel() {
    int idx = blockIdx.x * blockDim.x + threadIdx.x;   // over SB*64
    int d = idx & 63, s = idx >> 6;
    double ang = (double)s * exp((double)d * (-log(10000.0) / 64.0));
    g_cos[idx] = (float)cos(ang);
    g_sin[idx] = (float)sin(ang);
}

// t: [BH, S, 128] flattened, in-place rotate-half rope. total = BH*S*64
__global__ void rope_apply_kernel(float* __restrict__ t, int total) {
    int idx = blockIdx.x * blockDim.x + threadIdx.x;
    if (idx >= total) return;
    int d  = idx & 63;
    int s  = (idx >> 6) & (SB - 1);
    int bh = idx >> 17;                                // 64*2048 = 2^17
    float* base = t + ((size_t)bh * SB + s) * DH;
    float c  = g_cos[(s << 6) + d];
    float sn = g_sin[(s << 6) + d];
    float t1 = base[d], t2 = base[d + 64];
    base[d]      = t1 * c - t2 * sn;
    base[d + 64] = t2 * c + t1 * sn;
}

// ---------------- fp32 NT SGEMM:  C[M,N] = A[M,K] * B[N,K]^T + bias ----------------
// 128x128 block tile, BK=16, 256 threads, 8x8 per-thread microtile.
// MODE 0: C row-major [M,N].
// MODE 1: m=(b,s), n=(head,d)  ->  C[((b*NH+head)*SB + s)*DH + d]
template<int MODE>
__launch_bounds__(256, 2)
__global__ void gemm_nt(const float* __restrict__ A, const float* __restrict__ B,
                        const float* __restrict__ bias, float* __restrict__ C,
                        int N, int K, int NH) {
    __shared__ float As[16][128];
    __shared__ float Bs[16][128];
    const int tid = threadIdx.x;
    const int tx = tid & 15, ty = tid >> 4;
    const int m0 = blockIdx.y * 128;
    const int n0 = blockIdx.x * 128;

    float acc[8][8];
    #pragma unroll
    for (int i = 0; i < 8; i++)
        #pragma unroll
        for (int j = 0; j < 8; j++) acc[i][j] = 0.0f;

    for (int k0 = 0; k0 < K; k0 += 16) {
        #pragma unroll
        for (int tld = 0; tld < 2; tld++) {
            int idx4 = tid + tld * 256;          // 0..511 float4 units (128 rows x 4)
            int row  = idx4 >> 2;
            int kc   = (idx4 & 3) << 2;
            float4 av = *(const float4*)(A + (size_t)(m0 + row) * K + k0 + kc);
            As[kc+0][row] = av.x; As[kc+1][row] = av.y;
            As[kc+2][row] = av.z; As[kc+3][row] = av.w;
            float4 bv = *(const float4*)(B + (size_t)(n0 + row) * K + k0 + kc);
            Bs[kc+0][row] = bv.x; Bs[kc+1][row] = bv.y;
            Bs[kc+2][row] = bv.z; Bs[kc+3][row] = bv.w;
        }
        __syncthreads();
        #pragma unroll
        for (int kk = 0; kk < 16; kk++) {
            float af[8], bf[8];
            *(float4*)(af)     = *(const float4*)&As[kk][ty*8];
            *(float4*)(af + 4) = *(const float4*)&As[kk][ty*8 + 4];
            *(float4*)(bf)     = *(const float4*)&Bs[kk][tx*8];
            *(float4*)(bf + 4) = *(const float4*)&Bs[kk][tx*8 + 4];
            #pragma unroll
            for (int i = 0; i < 8; i++)
                #pragma unroll
                for (int j = 0; j < 8; j++)
                    acc[i][j] += af[i] * bf[j];
        }
        __syncthreads();
    }

    #pragma unroll
    for (int i = 0; i < 8; i++) {
        int m = m0 + ty*8 + i;
        int bidx = m >> 11;           // m / SB
        int s    = m & (SB - 1);
        #pragma unroll
        for (int j = 0; j < 8; j++) {
            int n = n0 + tx*8 + j;
            float v = acc[i][j] + (bias ? bias[n] : 0.0f);
            if (MODE == 0) {
                C[(size_t)m * N + n] = v;
            } else {
                int head = n >> 7, d = n & 127;
                C[(((size_t)bidx * NH + head) * SB + s) * DH + d] = v;
            }
        }
    }
}

// ---------------- fp32 flash attention, causal, 64x64 tiles, D=128 ----------------
// grid: (S/64, NHQ, NB); 256 threads. smem 83712 B.
__launch_bounds__(256, 2)
__global__ void attn_kernel(const float* __restrict__ q, const float* __restrict__ k,
                            const float* __restrict__ v, float* __restrict__ out) {
    extern __shared__ float sm[];
    float* Qs   = sm;                 // [128][64] transposed (dim-major)
    float* Ks   = sm + 8192;          // K phase: [128][64] transposed; V phase: [64][128]
    float* Ss   = sm + 16384;         // [64][68] scores/probs
    float* rowm = sm + 20736;         // [64]
    float* rowl = rowm + 64;          // [64]
    float* rowf = rowl + 64;          // [64]

    const int tid = threadIdx.x;
    const int tx = tid & 15, ty = tid >> 4;
    const int qt = gridDim.x - 1 - blockIdx.x;   // longest-work blocks first
    const int hq = blockIdx.y, b = blockIdx.z;
    const int g  = hq >> 2;                      // kv head

    const float* qbase = q + (((size_t)(b*NHQ + hq)) * SB + (size_t)qt*64) * DH;
    const float* kbase = k + ((size_t)(b*NHKV + g)) * SB * DH;
    const float* vbase = v + ((size_t)(b*NHKV + g)) * SB * DH;
    const float scale = 0.088388347648318447f;   // 1/sqrt(128)

    // load Q tile transposed, pre-scaled
    for (int i = tid; i < 64*32; i += 256) {
        int r = i >> 5, c4 = (i & 31) << 2;
        float4 t = *(const float4*)(qbase + r*DH + c4);
        Qs[(c4+0)*64 + r] = t.x * scale;
        Qs[(c4+1)*64 + r] = t.y * scale;
        Qs[(c4+2)*64 + r] = t.z * scale;
        Qs[(c4+3)*64 + r] = t.w * scale;
    }
    if (tid < 64) { rowm[tid] = -1e30f; rowl[tid] = 0.0f; }

    float acc[4][8];
    #pragma unroll
    for (int i = 0; i < 4; i++)
        #pragma unroll
        for (int j = 0; j < 8; j++) acc[i][j] = 0.0f;
    __syncthreads();

    const int ktiles = qt + 1;
    for (int kt = 0; kt < ktiles; kt++) {
        // ---- load K tile transposed ----
        const float* kb = kbase + (size_t)kt * 64 * DH;
        for (int i = tid; i < 64*32; i += 256) {
            int r = i >> 5, c4 = (i & 31) << 2;
            float4 t = *(const float4*)(kb + r*DH + c4);
            Ks[(c4+0)*64 + r] = t.x;
            Ks[(c4+1)*64 + r] = t.y;
            Ks[(c4+2)*64 + r] = t.z;
            Ks[(c4+3)*64 + r] = t.w;
        }
        __syncthreads();

        // ---- scores: thread -> rows ty*4+i, cols tx*4+j ----
        float sa[4][4];
        #pragma unroll
        for (int i = 0; i < 4; i++)
            #pragma unroll
            for (int j = 0; j < 4; j++) sa[i][j] = 0.0f;
        #pragma unroll 4
        for (int kk = 0; kk < 128; kk++) {
            float qa[4], kf[4];
            *(float4*)qa = *(const float4*)(Qs + kk*64 + ty*4);
            *(float4*)kf = *(const float4*)(Ks + kk*64 + tx*4);
            #pragma unroll
            for (int i = 0; i < 4; i++)
                #pragma unroll
                for (int j = 0; j < 4; j++)
                    sa[i][j] += qa[i] * kf[j];
        }

        // ---- mask + write to smem ----
        const int qrow0 = qt*64, kcol0 = kt*64;
        #pragma unroll
        for (int i = 0; i < 4; i++) {
            int qr = ty*4 + i;
            int lim = qrow0 + qr;
            float4 sv;
            sv.x = (kcol0 + tx*4 + 0 <= lim) ? sa[i][0] : -1e30f;
            sv.y = (kcol0 + tx*4 + 1 <= lim) ? sa[i][1] : -1e30f;
            sv.z = (kcol0 + tx*4 + 2 <= lim) ? sa[i][2] : -1e30f;
            sv.w = (kcol0 + tx*4 + 3 <= lim) ? sa[i][3] : -1e30f;
            *(float4*)(Ss + qr*68 + tx*4) = sv;
        }
        __syncthreads();   // Ks free, Ss visible

        // ---- load V tile (row-major) into Ks region ----
        const float* vb = vbase + (size_t)kt * 64 * DH;
        for (int i = tid; i < 64*32; i += 256) {
            int r = i >> 5, c4 = (i & 31) << 2;
            *(float4*)(Ks + r*128 + c4) = *(const float4*)(vb + r*DH + c4);
        }

        // ---- online softmax: 4 threads per row ----
        {
            int row = tid >> 2, seg = (tid & 3) << 4;
            float* srow = Ss + row*68 + seg;
            float mloc = srow[0];
            #pragma unroll
            for (int c = 1; c < 16; c++) mloc = fmaxf(mloc, srow[c]);
            mloc = fmaxf(mloc, __shfl_xor_sync(0xffffffffu, mloc, 1));
            mloc = fmaxf(mloc, __shfl_xor_sync(0xffffffffu, mloc, 2));
            float mnew = fmaxf(rowm[row], mloc);
            float lloc = 0.0f;
            #pragma unroll
            for (int c = 0; c < 16; c++) {
                float p = __expf(srow[c] - mnew);
                srow[c] = p;
                lloc += p;
            }
            lloc += __shfl_xor_sync(0xffffffffu, lloc, 1);
            lloc += __shfl_xor_sync(0xffffffffu, lloc, 2);
            if ((tid & 3) == 0) {
                float f = __expf(rowm[row] - mnew);
                rowf[row] = f;
                rowl[row] = rowl[row] * f + lloc;
                rowm[row] = mnew;
            }
        }
        __syncthreads();   // V loaded, softmax done

        // ---- rescale + P @ V ----
        #pragma unroll
        for (int i = 0; i < 4; i++) {
            float f = rowf[ty*4 + i];
            #pragma unroll
            for (int d = 0; d < 8; d++) acc[i][d] *= f;
        }
        #pragma unroll 2
        for (int key = 0; key < 64; key++) {
            float p0 = Ss[(ty*4 + 0)*68 + key];
            float p1 = Ss[(ty*4 + 1)*68 + key];
            float p2 = Ss[(ty*4 + 2)*68 + key];
            float p3 = Ss[(ty*4 + 3)*68 + key];
            float vv[8];
            *(float4*)(vv)     = *(const float4*)(Ks + key*128 + tx*8);
            *(float4*)(vv + 4) = *(const float4*)(Ks + key*128 + tx*8 + 4);
            #pragma unroll
            for (int d = 0; d < 8; d++) {
                acc[0][d] += p0 * vv[d];
                acc[1][d] += p1 * vv[d];
                acc[2][d] += p2 * vv[d];
                acc[3][d] += p3 * vv[d];
            }
        }
        __syncthreads();   // before next tile overwrites Ks/Ss
    }

    // ---- epilogue: normalize, write [B,S,Hq*D] ----
    #pragma unroll
    for (int i = 0; i < 4; i++) {
        int qr = ty*4 + i;
        float inv = 1.0f / rowl[qr];
        int s = qt*64 + qr;
        float* op = out + ((size_t)b*SB + s) * (NHQ*DH) + hq*DH + tx*8;
        float4 o0 = make_float4(acc[i][0]*inv, acc[i][1]*inv, acc[i][2]*inv, acc[i][3]*inv);
        float4 o1 = make_float4(acc[i][4]*inv, acc[i][5]*inv, acc[i][6]*inv, acc[i][7]*inv);
        *(float4*)(op)     = o0;
        *(float4*)(op + 4) = o1;
    }
}

// ---------------- launch ----------------
extern "C" void kernel_launch(void* const* d_in, const int* in_sizes, int n_in,
                              void* d_out, int out_size) {
    const float* x  = (const float*)d_in[0];
    const float* qW = (const float*)d_in[1];
    const float* kW = (const float*)d_in[2];
    const float* vW = (const float*)d_in[3];
    const float* qb = (const float*)d_in[4];
    const float* kb = (const float*)d_in[5];
    const float* vb = (const float*)d_in[6];
    const float* oW = (const float*)d_in[7];
    const float* lw = (const float*)d_in[8];
    float* outp = (float*)d_out;

    float *h, *qbuf, *kbuf, *vbuf, *ao;
    cudaGetSymbolAddress((void**)&h,    g_h);
    cudaGetSymbolAddress((void**)&qbuf, g_q);
    cudaGetSymbolAddress((void**)&kbuf, g_k);
    cudaGetSymbolAddress((void**)&vbuf, g_v);
    cudaGetSymbolAddress((void**)&ao,   g_ao);

    rmsnorm_kernel<<<NB*SB, 256>>>(x, lw, h);
    rope_table_kernel<<<(SB*64)/256, 256>>>();

    // QKV projections (write head-major [B,H,S,D] directly)
    gemm_nt<1><<<dim3(16, 32), 256>>>(h, qW, qb, qbuf, NHQ*DH,  HID, NHQ);
    gemm_nt<1><<<dim3(4,  32), 256>>>(h, kW, kb, kbuf, NHKV*DH, HID, NHKV);
    gemm_nt<1><<<dim3(4,  32), 256>>>(h, vW, vb, vbuf, NHKV*DH, HID, NHKV);

    rope_apply_kernel<<<(NB*NHQ *SB*64)/256, 256>>>(qbuf, NB*NHQ *SB*64);
    rope_apply_kernel<<<(NB*NHKV*SB*64)/256, 256>>>(kbuf, NB*NHKV*SB*64);

    cudaFuncSetAttribute(attn_kernel, cudaFuncAttributeMaxDynamicSharedMemorySize, 84*1024);
    attn_kernel<<<dim3(SB/64, NHQ, NB), 256, 83712>>>(qbuf, kbuf, vbuf, ao);

    // output projection -> d_out  [B*S, HID]
    gemm_nt<0><<<dim3(16, 32), 256>>>(ao, oW, nullptr, outp, HID, NHQ*DH, 0);
}

// round 8
// speedup vs baseline: 1.7967x; 1.7967x over previous
#include <cuda_runtime.h>
#include <cuda_fp16.h>
#include <mma.h>
#include <math.h>

using namespace nvcuda;

#define SB   2048   // sequence length
#define HID  2048   // hidden dim
#define NHQ  16
#define NHKV 4
#define DH   128
#define NB   2

// ---------------- scratch (device globals; no allocation allowed) ----------------
__device__ __half g_hh [(size_t)NB*SB*HID];       // rmsnorm output fp16   16.8 MB
__device__ float  g_q  [(size_t)NB*NHQ *SB*DH];   // q [B,Hq,S,D] fp32     33.5 MB
__device__ float  g_k  [(size_t)NB*NHKV*SB*DH];   // k [B,Hkv,S,D]          8.4 MB
__device__ float  g_v  [(size_t)NB*NHKV*SB*DH];   // v [B,Hkv,S,D]          8.4 MB
__device__ __half g_aoh[(size_t)NB*SB*NHQ*DH];    // attn out fp16         16.8 MB
__device__ __half g_wqh[(size_t)NHQ*DH*HID];      // q_project fp16         8.4 MB
__device__ __half g_wkh[(size_t)NHKV*DH*HID];     //                        2.1 MB
__device__ __half g_wvh[(size_t)NHKV*DH*HID];     //                        2.1 MB
__device__ __half g_woh[(size_t)HID*NHQ*DH];      //                        8.4 MB
__device__ float  g_cos[SB*64];
__device__ float  g_sin[SB*64];

// ---------------- fp32 -> fp16 convert ----------------
__global__ void f2h_kernel(const float* __restrict__ in, __half* __restrict__ out, int n) {
    int i = (blockIdx.x * blockDim.x + threadIdx.x) * 4;
    if (i >= n) return;
    float4 v = *(const float4*)(in + i);
    __half2* o = (__half2*)(out + i);
    o[0] = __floats2half2_rn(v.x, v.y);
    o[1] = __floats2half2_rn(v.z, v.w);
}

// ---------------- RMSNorm (fp32 in -> fp16 out) ----------------
__global__ void rmsnorm_kernel(const float* __restrict__ x,
                               const float* __restrict__ w,
                               __half* __restrict__ out) {
    int row = blockIdx.x;
    int t = threadIdx.x;
    const float4* xr = (const float4*)(x + (size_t)row * HID);
    __half2*      op = (__half2*)(out + (size_t)row * HID);
    const float4* w4 = (const float4*)w;

    float4 va = xr[t];
    float4 vb = xr[t + 256];
    float ss = va.x*va.x + va.y*va.y + va.z*va.z + va.w*va.w
             + vb.x*vb.x + vb.y*vb.y + vb.z*vb.z + vb.w*vb.w;

    __shared__ float red[8];
    #pragma unroll
    for (int o = 16; o; o >>= 1) ss += __shfl_xor_sync(0xffffffffu, ss, o);
    if ((t & 31) == 0) red[t >> 5] = ss;
    __syncthreads();
    float tot = red[0]+red[1]+red[2]+red[3]+red[4]+red[5]+red[6]+red[7];
    float inv = rsqrtf(tot * (1.0f/HID) + 1e-6f);

    float4 wa = w4[t], wb = w4[t + 256];
    op[t*2]           = __floats2half2_rn(va.x*inv*wa.x, va.y*inv*wa.y);
    op[t*2 + 1]       = __floats2half2_rn(va.z*inv*wa.z, va.w*inv*wa.w);
    op[(t+256)*2]     = __floats2half2_rn(vb.x*inv*wb.x, vb.y*inv*wb.y);
    op[(t+256)*2 + 1] = __floats2half2_rn(vb.z*inv*wb.z, vb.w*inv*wb.w);
}

// ---------------- RoPE ----------------
__global__ void rope_table_kernel() {
    int idx = blockIdx.x * blockDim.x + threadIdx.x;   // over SB*64
    int d = idx & 63, s = idx >> 6;
    double ang = (double)s * exp((double)d * (-log(10000.0) / 64.0));
    g_cos[idx] = (float)cos(ang);
    g_sin[idx] = (float)sin(ang);
}

__global__ void rope_apply_kernel(float* __restrict__ t, int total) {
    int idx = blockIdx.x * blockDim.x + threadIdx.x;
    if (idx >= total) return;
    int d  = idx & 63;
    int s  = (idx >> 6) & (SB - 1);
    int bh = idx >> 17;
    float* base = t + ((size_t)bh * SB + s) * DH;
    float c  = g_cos[(s << 6) + d];
    float sn = g_sin[(s << 6) + d];
    float t1 = base[d], t2 = base[d + 64];
    base[d]      = t1 * c - t2 * sn;
    base[d + 64] = t2 * c + t1 * sn;
}

// ---------------- WMMA fp16 tensor-core NT GEMM ----------------
// C[M,N] = A[M,K] * B[N,K]^T + bias
// BM=BN=128, BK=64 halfs. 256 threads = 8 warps (2x4), warp tile 64x32.
// wmma 16x16x16 fp16 -> fp32. Single-buffered smem tiles, stride 72.
// MODE 0: C row-major [M,N].   MODE 1: n=(head,d) -> C[((b*NH+head)*SB+s)*DH+d]
#define TSTRIDE 72   // halfs per tile row (64 data + 8 pad)

template<int MODE>
__launch_bounds__(256)
__global__ void wgemm_nt(const __half* __restrict__ A, const __half* __restrict__ B,
                         const float* __restrict__ bias, float* __restrict__ C,
                         int N, int K, int NH) {
    extern __shared__ __align__(16) char smraw[];
    __half* As = (__half*)smraw;                 // [128][TSTRIDE]
    __half* Bs = As + 128 * TSTRIDE;             // [128][TSTRIDE]
    float*  Cs = (float*)smraw;                  // [128][128] (epilogue reuse)

    const int tid = threadIdx.x;
    const int wid = tid >> 5;
    const int m0 = blockIdx.y * 128;
    const int n0 = blockIdx.x * 128;
    const int wm = (wid >> 2) * 64;              // warp row offset in tile
    const int wn = (wid & 3) * 32;               // warp col offset in tile

    wmma::fragment<wmma::accumulator, 16, 16, 16, float> cfrag[4][2];
    #pragma unroll
    for (int i = 0; i < 4; i++)
        #pragma unroll
        for (int j = 0; j < 2; j++)
            wmma::fill_fragment(cfrag[i][j], 0.0f);

    const int KT = K >> 6;
    for (int kt = 0; kt < KT; kt++) {
        const int k0 = kt << 6;
        // load A,B tiles: 1024 16B-chunks each, 4 per thread per matrix
        #pragma unroll
        for (int i = 0; i < 4; i++) {
            int chunk = tid + i * 256;           // 0..1023
            int trow  = chunk >> 3;              // 0..127
            int tcol8 = (chunk & 7) << 3;        // half index 0,8,...,56
            *(uint4*)(As + trow * TSTRIDE + tcol8) =
                *(const uint4*)(A + (size_t)(m0 + trow) * K + k0 + tcol8);
            *(uint4*)(Bs + trow * TSTRIDE + tcol8) =
                *(const uint4*)(B + (size_t)(n0 + trow) * K + k0 + tcol8);
        }
        __syncthreads();

        #pragma unroll
        for (int kk = 0; kk < 4; kk++) {
            wmma::fragment<wmma::matrix_a, 16, 16, 16, __half, wmma::row_major> afrag[4];
            wmma::fragment<wmma::matrix_b, 16, 16, 16, __half, wmma::col_major> bfrag[2];
            #pragma unroll
            for (int i = 0; i < 4; i++)
                wmma::load_matrix_sync(afrag[i], As + (wm + i*16) * TSTRIDE + kk*16, TSTRIDE);
            #pragma unroll
            for (int j = 0; j < 2; j++)
                wmma::load_matrix_sync(bfrag[j], Bs + (wn + j*16) * TSTRIDE + kk*16, TSTRIDE);
            #pragma unroll
            for (int i = 0; i < 4; i++)
                #pragma unroll
                for (int j = 0; j < 2; j++)
                    wmma::mma_sync(cfrag[i][j], afrag[i], bfrag[j], cfrag[i][j]);
        }
        __syncthreads();
    }

    // ---- epilogue: frags -> smem fp32, then bias + scatter ----
    #pragma unroll
    for (int i = 0; i < 4; i++)
        #pragma unroll
        for (int j = 0; j < 2; j++)
            wmma::store_matrix_sync(Cs + (wm + i*16) * 128 + wn + j*16,
                                    cfrag[i][j], 128, wmma::mem_row_major);
    __syncthreads();

    // 128x128 floats = 4096 float4 units, 16 per thread
    #pragma unroll
    for (int u = 0; u < 16; u++) {
        int unit = tid + u * 256;
        int mrow = unit >> 5;                    // 0..127
        int ncol = (unit & 31) << 2;             // 0,4,...,124
        float4 v = *(float4*)(Cs + mrow * 128 + ncol);
        int n = n0 + ncol;
        if (bias) {
            v.x += bias[n];
            v.y += bias[n + 1];
            v.z += bias[n + 2];
            v.w += bias[n + 3];
        }
        int m = m0 + mrow;
        if (MODE == 0) {
            *(float4*)(C + (size_t)m * N + n) = v;
        } else {
            int head = n >> 7, dcol = n & 127;
            int bidx = m >> 11, srow = m & (SB - 1);
            *(float4*)(C + (((size_t)bidx * NH + head) * SB + srow) * DH + dcol) = v;
        }
    }
}

// ---------------- fp32 flash attention, causal, 64x64 tiles, D=128 ----------------
// grid: (S/64, NHQ, NB); 256 threads. smem 83712 B. Output fp16.
__launch_bounds__(256, 2)
__global__ void attn_kernel(const float* __restrict__ q, const float* __restrict__ k,
                            const float* __restrict__ v, __half* __restrict__ out) {
    extern __shared__ float smf[];
    float* Qs   = smf;                 // [128][64] transposed (dim-major)
    float* Ks   = smf + 8192;          // K phase: [128][64] transposed; V phase: [64][128]
    float* Ss   = smf + 16384;         // [64][68] scores/probs
    float* rowm = smf + 20736;
    float* rowl = rowm + 64;
    float* rowf = rowl + 64;

    const int tid = threadIdx.x;
    const int tx = tid & 15, ty = tid >> 4;
    const int qt = gridDim.x - 1 - blockIdx.x;
    const int hq = blockIdx.y, b = blockIdx.z;
    const int g  = hq >> 2;

    const float* qbase = q + (((size_t)(b*NHQ + hq)) * SB + (size_t)qt*64) * DH;
    const float* kbase = k + ((size_t)(b*NHKV + g)) * SB * DH;
    const float* vbase = v + ((size_t)(b*NHKV + g)) * SB * DH;
    const float scale = 0.088388347648318447f;   // 1/sqrt(128)

    for (int i = tid; i < 64*32; i += 256) {
        int r = i >> 5, c4 = (i & 31) << 2;
        float4 tq = *(const float4*)(qbase + r*DH + c4);
        Qs[(c4+0)*64 + r] = tq.x * scale;
        Qs[(c4+1)*64 + r] = tq.y * scale;
        Qs[(c4+2)*64 + r] = tq.z * scale;
        Qs[(c4+3)*64 + r] = tq.w * scale;
    }
    if (tid < 64) { rowm[tid] = -1e30f; rowl[tid] = 0.0f; }

    float acc[4][8];
    #pragma unroll
    for (int i = 0; i < 4; i++)
        #pragma unroll
        for (int j = 0; j < 8; j++) acc[i][j] = 0.0f;
    __syncthreads();

    const int ktiles = qt + 1;
    for (int kt = 0; kt < ktiles; kt++) {
        const float* kb = kbase + (size_t)kt * 64 * DH;
        for (int i = tid; i < 64*32; i += 256) {
            int r = i >> 5, c4 = (i & 31) << 2;
            float4 tk = *(const float4*)(kb + r*DH + c4);
            Ks[(c4+0)*64 + r] = tk.x;
            Ks[(c4+1)*64 + r] = tk.y;
            Ks[(c4+2)*64 + r] = tk.z;
            Ks[(c4+3)*64 + r] = tk.w;
        }
        __syncthreads();

        float sacc[4][4];
        #pragma unroll
        for (int i = 0; i < 4; i++)
            #pragma unroll
            for (int j = 0; j < 4; j++) sacc[i][j] = 0.0f;
        #pragma unroll 4
        for (int kk = 0; kk < 128; kk++) {
            float qv[4], kv[4];
            *(float4*)qv = *(const float4*)(Qs + kk*64 + ty*4);
            *(float4*)kv = *(const float4*)(Ks + kk*64 + tx*4);
            #pragma unroll
            for (int i = 0; i < 4; i++)
                #pragma unroll
                for (int j = 0; j < 4; j++)
                    sacc[i][j] += qv[i] * kv[j];
        }

        const int qrow0 = qt*64, kcol0 = kt*64;
        #pragma unroll
        for (int i = 0; i < 4; i++) {
            int qr = ty*4 + i;
            int lim = qrow0 + qr;
            float4 sv;
            sv.x = (kcol0 + tx*4 + 0 <= lim) ? sacc[i][0] : -1e30f;
            sv.y = (kcol0 + tx*4 + 1 <= lim) ? sacc[i][1] : -1e30f;
            sv.z = (kcol0 + tx*4 + 2 <= lim) ? sacc[i][2] : -1e30f;
            sv.w = (kcol0 + tx*4 + 3 <= lim) ? sacc[i][3] : -1e30f;
            *(float4*)(Ss + qr*68 + tx*4) = sv;
        }
        __syncthreads();

        const float* vbp = vbase + (size_t)kt * 64 * DH;
        for (int i = tid; i < 64*32; i += 256) {
            int r = i >> 5, c4 = (i & 31) << 2;
            *(float4*)(Ks + r*128 + c4) = *(const float4*)(vbp + r*DH + c4);
        }

        {
            int srw = tid >> 2, seg = (tid & 3) << 4;
            float* srow = Ss + srw*68 + seg;
            float mloc = srow[0];
            #pragma unroll
            for (int c = 1; c < 16; c++) mloc = fmaxf(mloc, srow[c]);
            mloc = fmaxf(mloc, __shfl_xor_sync(0xffffffffu, mloc, 1));
            mloc = fmaxf(mloc, __shfl_xor_sync(0xffffffffu, mloc, 2));
            float mnew = fmaxf(rowm[srw], mloc);
            float lloc = 0.0f;
            #pragma unroll
            for (int c = 0; c < 16; c++) {
                float p = __expf(srow[c] - mnew);
                srow[c] = p;
                lloc += p;
            }
            lloc += __shfl_xor_sync(0xffffffffu, lloc, 1);
            lloc += __shfl_xor_sync(0xffffffffu, lloc, 2);
            if ((tid & 3) == 0) {
                float f = __expf(rowm[srw] - mnew);
                rowf[srw] = f;
                rowl[srw] = rowl[srw] * f + lloc;
                rowm[srw] = mnew;
            }
        }
        __syncthreads();

        #pragma unroll
        for (int i = 0; i < 4; i++) {
            float f = rowf[ty*4 + i];
            #pragma unroll
            for (int d = 0; d < 8; d++) acc[i][d] *= f;
        }
        #pragma unroll 2
        for (int key = 0; key < 64; key++) {
            float p0 = Ss[(ty*4 + 0)*68 + key];
            float p1 = Ss[(ty*4 + 1)*68 + key];
            float p2 = Ss[(ty*4 + 2)*68 + key];
            float p3 = Ss[(ty*4 + 3)*68 + key];
            float vv[8];
            *(float4*)(vv)     = *(const float4*)(Ks + key*128 + tx*8);
            *(float4*)(vv + 4) = *(const float4*)(Ks + key*128 + tx*8 + 4);
            #pragma unroll
            for (int d = 0; d < 8; d++) {
                acc[0][d] += p0 * vv[d];
                acc[1][d] += p1 * vv[d];
                acc[2][d] += p2 * vv[d];
                acc[3][d] += p3 * vv[d];
            }
        }
        __syncthreads();
    }

    // ---- epilogue: normalize, write fp16 [B,S,Hq*D] ----
    #pragma unroll
    for (int i = 0; i < 4; i++) {
        int qr = ty*4 + i;
        float inv = 1.0f / rowl[qr];
        int srow = qt*64 + qr;
        __half* op = out + ((size_t)b*SB + srow) * (NHQ*DH) + hq*DH + tx*8;
        union { uint4 pu; __half2 ph[4]; } pk;
        pk.ph[0] = __floats2half2_rn(acc[i][0]*inv, acc[i][1]*inv);
        pk.ph[1] = __floats2half2_rn(acc[i][2]*inv, acc[i][3]*inv);
        pk.ph[2] = __floats2half2_rn(acc[i][4]*inv, acc[i][5]*inv);
        pk.ph[3] = __floats2half2_rn(acc[i][6]*inv, acc[i][7]*inv);
        *(uint4*)op = pk.pu;
    }
}

// ---------------- launch ----------------
extern "C" void kernel_launch(void* const* d_in, const int* in_sizes, int n_in,
                              void* d_out, int out_size) {
    const float* x  = (const float*)d_in[0];
    const float* qW = (const float*)d_in[1];
    const float* kW = (const float*)d_in[2];
    const float* vW = (const float*)d_in[3];
    const float* qb = (const float*)d_in[4];
    const float* kb = (const float*)d_in[5];
    const float* vb = (const float*)d_in[6];
    const float* oW = (const float*)d_in[7];
    const float* lw = (const float*)d_in[8];
    float* outp = (float*)d_out;

    __half *hhp, *wqh, *wkh, *wvh, *woh, *aoh;
    float *qbuf, *kbuf, *vbuf;
    cudaGetSymbolAddress((void**)&hhp,  g_hh);
    cudaGetSymbolAddress((void**)&wqh,  g_wqh);
    cudaGetSymbolAddress((void**)&wkh,  g_wkh);
    cudaGetSymbolAddress((void**)&wvh,  g_wvh);
    cudaGetSymbolAddress((void**)&woh,  g_woh);
    cudaGetSymbolAddress((void**)&aoh,  g_aoh);
    cudaGetSymbolAddress((void**)&qbuf, g_q);
    cudaGetSymbolAddress((void**)&kbuf, g_k);
    cudaGetSymbolAddress((void**)&vbuf, g_v);

    cudaFuncSetAttribute(wgemm_nt<0>, cudaFuncAttributeMaxDynamicSharedMemorySize, 65536);
    cudaFuncSetAttribute(wgemm_nt<1>, cudaFuncAttributeMaxDynamicSharedMemorySize, 65536);
    cudaFuncSetAttribute(attn_kernel, cudaFuncAttributeMaxDynamicSharedMemorySize, 84*1024);

    rmsnorm_kernel<<<NB*SB, 256>>>(x, lw, hhp);
    rope_table_kernel<<<(SB*64)/256, 256>>>();

    // weight conversions fp32 -> fp16
    f2h_kernel<<<(NHQ*DH*HID)/1024,  256>>>(qW, wqh, NHQ*DH*HID);
    f2h_kernel<<<(NHKV*DH*HID)/1024, 256>>>(kW, wkh, NHKV*DH*HID);
    f2h_kernel<<<(NHKV*DH*HID)/1024, 256>>>(vW, wvh, NHKV*DH*HID);
    f2h_kernel<<<(HID*NHQ*DH)/1024,  256>>>(oW, woh, HID*NHQ*DH);

    // QKV projections (tensor cores; write head-major [B,H,S,D] fp32)
    wgemm_nt<1><<<dim3(16, 32), 256, 65536>>>(hhp, wqh, qb, qbuf, NHQ*DH,  HID, NHQ);
    wgemm_nt<1><<<dim3(4,  32), 256, 65536>>>(hhp, wkh, kb, kbuf, NHKV*DH, HID, NHKV);
    wgemm_nt<1><<<dim3(4,  32), 256, 65536>>>(hhp, wvh, vb, vbuf, NHKV*DH, HID, NHKV);

    rope_apply_kernel<<<(NB*NHQ *SB*64)/256, 256>>>(qbuf, NB*NHQ *SB*64);
    rope_apply_kernel<<<(NB*NHKV*SB*64)/256, 256>>>(kbuf, NB*NHKV*SB*64);

    attn_kernel<<<dim3(SB/64, NHQ, NB), 256, 83712>>>(qbuf, kbuf, vbuf, aoh);

    // output projection -> d_out [B*S, HID]
    wgemm_nt<0><<<dim3(16, 32), 256, 65536>>>(aoh, woh, nullptr, outp, HID, NHQ*DH, 0);
}

// round 10
// speedup vs baseline: 4.4477x; 2.4755x over previous
#include <cuda_runtime.h>
#include <cuda_fp16.h>
#include <mma.h>
#include <math.h>

using namespace nvcuda;

#define SB   2048   // sequence length
#define HID  2048   // hidden dim
#define NHQ  16
#define NHKV 4
#define DH   128
#define NB   2

// ---------------- scratch (device globals; no allocation allowed) ----------------
__device__ __half g_hh [(size_t)NB*SB*HID];       // rmsnorm output fp16   16.8 MB
__device__ float  g_q  [(size_t)NB*NHQ *SB*DH];   // q [B,Hq,S,D] fp32     33.5 MB
__device__ float  g_k  [(size_t)NB*NHKV*SB*DH];   // k [B,Hkv,S,D]          8.4 MB
__device__ float  g_v  [(size_t)NB*NHKV*SB*DH];   // v [B,Hkv,S,D]          8.4 MB
__device__ __half g_aoh[(size_t)NB*SB*NHQ*DH];    // attn out fp16         16.8 MB
__device__ __half g_wqh[(size_t)NHQ*DH*HID];      // q_project fp16         8.4 MB
__device__ __half g_wkh[(size_t)NHKV*DH*HID];     //                        2.1 MB
__device__ __half g_wvh[(size_t)NHKV*DH*HID];     //                        2.1 MB
__device__ __half g_woh[(size_t)HID*NHQ*DH];      //                        8.4 MB
__device__ float  g_cos[SB*64];
__device__ float  g_sin[SB*64];

// ---------------- fp32 -> fp16 convert ----------------
__global__ void f2h_kernel(const float* __restrict__ in, __half* __restrict__ out, int n) {
    int i = (blockIdx.x * blockDim.x + threadIdx.x) * 4;
    if (i >= n) return;
    float4 v = *(const float4*)(in + i);
    __half2* o = (__half2*)(out + i);
    o[0] = __floats2half2_rn(v.x, v.y);
    o[1] = __floats2half2_rn(v.z, v.w);
}

// ---------------- RMSNorm (fp32 in -> fp16 out) ----------------
__global__ void rmsnorm_kernel(const float* __restrict__ x,
                               const float* __restrict__ w,
                               __half* __restrict__ out) {
    int row = blockIdx.x;
    int t = threadIdx.x;
    const float4* xr = (const float4*)(x + (size_t)row * HID);
    __half2*      op = (__half2*)(out + (size_t)row * HID);
    const float4* w4 = (const float4*)w;

    float4 va = xr[t];
    float4 vb = xr[t + 256];
    float ss = va.x*va.x + va.y*va.y + va.z*va.z + va.w*va.w
             + vb.x*vb.x + vb.y*vb.y + vb.z*vb.z + vb.w*vb.w;

    __shared__ float red[8];
    #pragma unroll
    for (int o = 16; o; o >>= 1) ss += __shfl_xor_sync(0xffffffffu, ss, o);
    if ((t & 31) == 0) red[t >> 5] = ss;
    __syncthreads();
    float tot = red[0]+red[1]+red[2]+red[3]+red[4]+red[5]+red[6]+red[7];
    float inv = rsqrtf(tot * (1.0f/HID) + 1e-6f);

    float4 wa = w4[t], wb = w4[t + 256];
    op[t*2]           = __floats2half2_rn(va.x*inv*wa.x, va.y*inv*wa.y);
    op[t*2 + 1]       = __floats2half2_rn(va.z*inv*wa.z, va.w*inv*wa.w);
    op[(t+256)*2]     = __floats2half2_rn(vb.x*inv*wb.x, vb.y*inv*wb.y);
    op[(t+256)*2 + 1] = __floats2half2_rn(vb.z*inv*wb.z, vb.w*inv*wb.w);
}

// ---------------- RoPE ----------------
__global__ void rope_table_kernel() {
    int idx = blockIdx.x * blockDim.x + threadIdx.x;   // over SB*64
    int d = idx & 63, s = idx >> 6;
    double ang = (double)s * exp((double)d * (-log(10000.0) / 64.0));
    g_cos[idx] = (float)cos(ang);
    g_sin[idx] = (float)sin(ang);
}

__global__ void rope_apply_kernel(float* __restrict__ t, int total) {
    int idx = blockIdx.x * blockDim.x + threadIdx.x;
    if (idx >= total) return;
    int d  = idx & 63;
    int s  = (idx >> 6) & (SB - 1);
    int bh = idx >> 17;
    float* base = t + ((size_t)bh * SB + s) * DH;
    float c  = g_cos[(s << 6) + d];
    float sn = g_sin[(s << 6) + d];
    float t1 = base[d], t2 = base[d + 64];
    base[d]      = t1 * c - t2 * sn;
    base[d + 64] = t2 * c + t1 * sn;
}

// ---------------- WMMA fp16 tensor-core NT GEMM ----------------
// C[M,N] = A[M,K] * B[N,K]^T + bias
// BM=BN=128, BK=64 halfs. 256 threads = 8 warps (2x4), warp tile 64x32.
// MODE 0: C row-major [M,N].   MODE 1: n=(head,d) -> C[((b*NH+head)*SB+s)*DH+d]
#define TSTRIDE 72   // halfs per tile row (64 data + 8 pad)

template<int MODE>
__launch_bounds__(256)
__global__ void wgemm_nt(const __half* __restrict__ A, const __half* __restrict__ B,
                         const float* __restrict__ bias, float* __restrict__ C,
                         int N, int K, int NH) {
    extern __shared__ __align__(16) char smraw[];
    __half* As = (__half*)smraw;                 // [128][TSTRIDE]
    __half* Bs = As + 128 * TSTRIDE;             // [128][TSTRIDE]
    float*  Cs = (float*)smraw;                  // [128][128] (epilogue reuse)

    const int tid = threadIdx.x;
    const int wid = tid >> 5;
    const int m0 = blockIdx.y * 128;
    const int n0 = blockIdx.x * 128;
    const int wm = (wid >> 2) * 64;
    const int wn = (wid & 3) * 32;

    wmma::fragment<wmma::accumulator, 16, 16, 16, float> cfrag[4][2];
    #pragma unroll
    for (int i = 0; i < 4; i++)
        #pragma unroll
        for (int j = 0; j < 2; j++)
            wmma::fill_fragment(cfrag[i][j], 0.0f);

    const int KT = K >> 6;
    for (int kt = 0; kt < KT; kt++) {
        const int k0 = kt << 6;
        #pragma unroll
        for (int i = 0; i < 4; i++) {
            int chunk = tid + i * 256;
            int trow  = chunk >> 3;
            int tcol8 = (chunk & 7) << 3;
            *(uint4*)(As + trow * TSTRIDE + tcol8) =
                *(const uint4*)(A + (size_t)(m0 + trow) * K + k0 + tcol8);
            *(uint4*)(Bs + trow * TSTRIDE + tcol8) =
                *(const uint4*)(B + (size_t)(n0 + trow) * K + k0 + tcol8);
        }
        __syncthreads();

        #pragma unroll
        for (int kk = 0; kk < 4; kk++) {
            wmma::fragment<wmma::matrix_a, 16, 16, 16, __half, wmma::row_major> afrag[4];
            wmma::fragment<wmma::matrix_b, 16, 16, 16, __half, wmma::col_major> bfrag[2];
            #pragma unroll
            for (int i = 0; i < 4; i++)
                wmma::load_matrix_sync(afrag[i], As + (wm + i*16) * TSTRIDE + kk*16, TSTRIDE);
            #pragma unroll
            for (int j = 0; j < 2; j++)
                wmma::load_matrix_sync(bfrag[j], Bs + (wn + j*16) * TSTRIDE + kk*16, TSTRIDE);
            #pragma unroll
            for (int i = 0; i < 4; i++)
                #pragma unroll
                for (int j = 0; j < 2; j++)
                    wmma::mma_sync(cfrag[i][j], afrag[i], bfrag[j], cfrag[i][j]);
        }
        __syncthreads();
    }

    #pragma unroll
    for (int i = 0; i < 4; i++)
        #pragma unroll
        for (int j = 0; j < 2; j++)
            wmma::store_matrix_sync(Cs + (wm + i*16) * 128 + wn + j*16,
                                    cfrag[i][j], 128, wmma::mem_row_major);
    __syncthreads();

    #pragma unroll
    for (int u = 0; u < 16; u++) {
        int unit = tid + u * 256;
        int mrow = unit >> 5;
        int ncol = (unit & 31) << 2;
        float4 v = *(float4*)(Cs + mrow * 128 + ncol);
        int n = n0 + ncol;
        if (bias) {
            v.x += bias[n];
            v.y += bias[n + 1];
            v.z += bias[n + 2];
            v.w += bias[n + 3];
        }
        int m = m0 + mrow;
        if (MODE == 0) {
            *(float4*)(C + (size_t)m * N + n) = v;
        } else {
            int head = n >> 7, dcol = n & 127;
            int bidx = m >> 11, srow = m & (SB - 1);
            *(float4*)(C + (((size_t)bidx * NH + head) * SB + srow) * DH + dcol) = v;
        }
    }
}

// ---------------- WMMA fp16 flash attention, causal ----------------
// Per block: 128 q-rows x one head. 512 threads = 16 warps. Tiles of 64 keys.
// Q,K,V fp32 in gmem -> fp16 smem. QK^T and P@V on tensor cores (fp32 accum).
// Softmax fp32. O accumulator in explicit per-thread registers (rescale by f).
#define ATT_SMEM 192000

__launch_bounds__(512)
__global__ void attn_wmma_kernel(const float* __restrict__ q, const float* __restrict__ k,
                                 const float* __restrict__ v, __half* __restrict__ out) {
    extern __shared__ __align__(16) char smb[];
    __half* Qs  = (__half*)smb;
    __half* Ks  = Qs + 128*136;
    __half* Vs  = Ks + 64*136;
    float*  Sf  = (float*)(Vs + 64*136);
    __half* Pf  = (__half*)(Sf + 128*68);
    float*  PVp = (float*)(Pf + 128*72);
    float*  rowm = PVp + 128*132;
    float*  rowl = rowm + 128;
    float*  rowf = rowl + 128;

    const int tid = threadIdx.x;
    const int wid = tid >> 5;
    const int qt = 15 - blockIdx.x;              // longest-work blocks first
    const int hq = blockIdx.y, b = blockIdx.z;
    const int g  = hq >> 2;

    const float* qbase = q + (((size_t)(b*NHQ + hq)) * SB + (size_t)qt*128) * DH;
    const float* kbase = k + ((size_t)(b*NHKV + g)) * SB * DH;
    const float* vbase = v + ((size_t)(b*NHKV + g)) * SB * DH;
    const float scale = 0.088388347648318447f;   // 1/sqrt(128)

    // load Q tile fp32 -> fp16 (pre-scaled)
    for (int i = tid; i < 128*32; i += 512) {
        int r = i >> 5, c4 = (i & 31) << 2;
        float4 tq = *(const float4*)(qbase + r*DH + c4);
        uint2 pk;
        ((__half2*)&pk)[0] = __floats2half2_rn(tq.x*scale, tq.y*scale);
        ((__half2*)&pk)[1] = __floats2half2_rn(tq.z*scale, tq.w*scale);
        *(uint2*)(Qs + r*136 + c4) = pk;
    }
    if (tid < 128) { rowm[tid] = -1e30f; rowl[tid] = 0.0f; }

    float acc[32];
    #pragma unroll
    for (int j = 0; j < 32; j++) acc[j] = 0.0f;

    const int arow = tid >> 2;                   // accumulate/softmax row
    const int acol = (tid & 3) << 5;             // accumulate col base (32 cols)
    const int sseg = (tid & 3) << 4;             // softmax col base (16 cols)

    const int wr = wid >> 1;                     // warp row group (0..7) -> rows wr*16
    const int wc = wid & 1;                      // warp col group

    const int kts = 2 * (qt + 1);
    for (int kt = 0; kt < kts; kt++) {
        // ---- load K,V tile fp32 -> fp16 ----  (also closes prev accumulate)
        __syncthreads();
        const float* kb = kbase + (size_t)kt * 64 * DH;
        const float* vb = vbase + (size_t)kt * 64 * DH;
        for (int i = tid; i < 64*32; i += 512) {
            int r = i >> 5, c4 = (i & 31) << 2;
            float4 tk = *(const float4*)(kb + r*DH + c4);
            uint2 pk;
            ((__half2*)&pk)[0] = __floats2half2_rn(tk.x, tk.y);
            ((__half2*)&pk)[1] = __floats2half2_rn(tk.z, tk.w);
            *(uint2*)(Ks + r*136 + c4) = pk;
            float4 tv = *(const float4*)(vb + r*DH + c4);
            uint2 pv;
            ((__half2*)&pv)[0] = __floats2half2_rn(tv.x, tv.y);
            ((__half2*)&pv)[1] = __floats2half2_rn(tv.z, tv.w);
            *(uint2*)(Vs + r*136 + c4) = pv;
        }
        __syncthreads();

        // ---- QK^T: S[128,64], warp = 16 rows x 32 cols ----
        {
            wmma::fragment<wmma::accumulator, 16, 16, 16, float> sfr[2];
            wmma::fill_fragment(sfr[0], 0.0f);
            wmma::fill_fragment(sfr[1], 0.0f);
            #pragma unroll
            for (int kk = 0; kk < 8; kk++) {
                wmma::fragment<wmma::matrix_a, 16, 16, 16, __half, wmma::row_major> afr;
                wmma::fragment<wmma::matrix_b, 16, 16, 16, __half, wmma::col_major> bfr[2];
                wmma::load_matrix_sync(afr, Qs + (wr*16)*136 + kk*16, 136);
                #pragma unroll
                for (int j = 0; j < 2; j++)
                    wmma::load_matrix_sync(bfr[j], Ks + (wc*32 + j*16)*136 + kk*16, 136);
                #pragma unroll
                for (int j = 0; j < 2; j++)
                    wmma::mma_sync(sfr[j], afr, bfr[j], sfr[j]);
            }
            #pragma unroll
            for (int j = 0; j < 2; j++)
                wmma::store_matrix_sync(Sf + (wr*16)*68 + wc*32 + j*16, sfr[j], 68,
                                        wmma::mem_row_major);
        }
        __syncthreads();

        // ---- softmax: 4 threads per row, 16 cols each ----
        {
            const float* srow = Sf + arow*68 + sseg;
            const int qglob = qt*128 + arow;
            const int kcb = kt*64 + sseg;
            float vals[16];
            #pragma unroll
            for (int c = 0; c < 16; c++)
                vals[c] = (kcb + c <= qglob) ? srow[c] : -1e30f;
            float mloc = vals[0];
            #pragma unroll
            for (int c = 1; c < 16; c++) mloc = fmaxf(mloc, vals[c]);
            mloc = fmaxf(mloc, __shfl_xor_sync(0xffffffffu, mloc, 1));
            mloc = fmaxf(mloc, __shfl_xor_sync(0xffffffffu, mloc, 2));
            float mold = rowm[arow];
            float mnew = fmaxf(mold, mloc);
            float lloc = 0.0f;
            __half2* prow = (__half2*)(Pf + arow*72 + sseg);
            #pragma unroll
            for (int c = 0; c < 8; c++) {
                float p0 = __expf(vals[2*c]   - mnew);
                float p1 = __expf(vals[2*c+1] - mnew);
                lloc += p0 + p1;
                prow[c] = __floats2half2_rn(p0, p1);
            }
            lloc += __shfl_xor_sync(0xffffffffu, lloc, 1);
            lloc += __shfl_xor_sync(0xffffffffu, lloc, 2);
            if ((tid & 3) == 0) {
                float f = __expf(mold - mnew);
                rowf[arow] = f;
                rowl[arow] = rowl[arow] * f + lloc;
                rowm[arow] = mnew;
            }
        }
        __syncthreads();

        // ---- P@V: O[128,128], warp = 16 rows x 64 cols ----
        {
            wmma::fragment<wmma::accumulator, 16, 16, 16, float> ofr[4];
            #pragma unroll
            for (int j = 0; j < 4; j++) wmma::fill_fragment(ofr[j], 0.0f);
            #pragma unroll
            for (int kk = 0; kk < 4; kk++) {
                wmma::fragment<wmma::matrix_a, 16, 16, 16, __half, wmma::row_major> pfr;
                wmma::fragment<wmma::matrix_b, 16, 16, 16, __half, wmma::row_major> vfr[4];
                wmma::load_matrix_sync(pfr, Pf + (wr*16)*72 + kk*16, 72);
                #pragma unroll
                for (int j = 0; j < 4; j++)
                    wmma::load_matrix_sync(vfr[j], Vs + (kk*16)*136 + wc*64 + j*16, 136);
                #pragma unroll
                for (int j = 0; j < 4; j++)
                    wmma::mma_sync(ofr[j], pfr, vfr[j], ofr[j]);
            }
            #pragma unroll
            for (int j = 0; j < 4; j++)
                wmma::store_matrix_sync(PVp + (wr*16)*132 + wc*64 + j*16, ofr[j], 132,
                                        wmma::mem_row_major);
        }
        __syncthreads();

        // ---- accumulate: acc = acc*f + partial ----
        {
            float f = rowf[arow];
            const float* prow = PVp + arow*132 + acol;
            #pragma unroll
            for (int j4 = 0; j4 < 8; j4++) {
                float4 pv = *(const float4*)(prow + j4*4);
                acc[j4*4+0] = acc[j4*4+0]*f + pv.x;
                acc[j4*4+1] = acc[j4*4+1]*f + pv.y;
                acc[j4*4+2] = acc[j4*4+2]*f + pv.z;
                acc[j4*4+3] = acc[j4*4+3]*f + pv.w;
            }
        }
    }

    // ---- epilogue: normalize, write fp16 [B,S,Hq*D] ----
    {
        float inv = 1.0f / rowl[arow];
        int srow = qt*128 + arow;
        __half* op = out + ((size_t)b*SB + srow) * (NHQ*DH) + hq*DH + acol;
        #pragma unroll
        for (int j4 = 0; j4 < 4; j4++) {
            uint4 pk;
            ((__half2*)&pk)[0] = __floats2half2_rn(acc[j4*8+0]*inv, acc[j4*8+1]*inv);
            ((__half2*)&pk)[1] = __floats2half2_rn(acc[j4*8+2]*inv, acc[j4*8+3]*inv);
            ((__half2*)&pk)[2] = __floats2half2_rn(acc[j4*8+4]*inv, acc[j4*8+5]*inv);
            ((__half2*)&pk)[3] = __floats2half2_rn(acc[j4*8+6]*inv, acc[j4*8+7]*inv);
            *(uint4*)(op + j4*8) = pk;
        }
    }
}

// ---------------- launch ----------------
extern "C" void kernel_launch(void* const* d_in, const int* in_sizes, int n_in,
                              void* d_out, int out_size) {
    const float* x  = (const float*)d_in[0];
    const float* qW = (const float*)d_in[1];
    const float* kW = (const float*)d_in[2];
    const float* vW = (const float*)d_in[3];
    const float* qb = (const float*)d_in[4];
    const float* kb = (const float*)d_in[5];
    const float* vb = (const float*)d_in[6];
    const float* oW = (const float*)d_in[7];
    const float* lw = (const float*)d_in[8];
    float* outp = (float*)d_out;

    __half *hhp, *wqh, *wkh, *wvh, *woh, *aoh;
    float *qbuf, *kbuf, *vbuf;
    cudaGetSymbolAddress((void**)&hhp,  g_hh);
    cudaGetSymbolAddress((void**)&wqh,  g_wqh);
    cudaGetSymbolAddress((void**)&wkh,  g_wkh);
    cudaGetSymbolAddress((void**)&wvh,  g_wvh);
    cudaGetSymbolAddress((void**)&woh,  g_woh);
    cudaGetSymbolAddress((void**)&aoh,  g_aoh);
    cudaGetSymbolAddress((void**)&qbuf, g_q);
    cudaGetSymbolAddress((void**)&kbuf, g_k);
    cudaGetSymbolAddress((void**)&vbuf, g_v);

    cudaFuncSetAttribute(wgemm_nt<0>, cudaFuncAttributeMaxDynamicSharedMemorySize, 65536);
    cudaFuncSetAttribute(wgemm_nt<1>, cudaFuncAttributeMaxDynamicSharedMemorySize, 65536);
    cudaFuncSetAttribute(attn_wmma_kernel, cudaFuncAttributeMaxDynamicSharedMemorySize, ATT_SMEM);

    rmsnorm_kernel<<<NB*SB, 256>>>(x, lw, hhp);
    rope_table_kernel<<<(SB*64)/256, 256>>>();

    // weight conversions fp32 -> fp16
    f2h_kernel<<<(NHQ*DH*HID)/1024,  256>>>(qW, wqh, NHQ*DH*HID);
    f2h_kernel<<<(NHKV*DH*HID)/1024, 256>>>(kW, wkh, NHKV*DH*HID);
    f2h_kernel<<<(NHKV*DH*HID)/1024, 256>>>(vW, wvh, NHKV*DH*HID);
    f2h_kernel<<<(HID*NHQ*DH)/1024,  256>>>(oW, woh, HID*NHQ*DH);

    // QKV projections (tensor cores; write head-major [B,H,S,D] fp32)
    wgemm_nt<1><<<dim3(16, 32), 256, 65536>>>(hhp, wqh, qb, qbuf, NHQ*DH,  HID, NHQ);
    wgemm_nt<1><<<dim3(4,  32), 256, 65536>>>(hhp, wkh, kb, kbuf, NHKV*DH, HID, NHKV);
    wgemm_nt<1><<<dim3(4,  32), 256, 65536>>>(hhp, wvh, vb, vbuf, NHKV*DH, HID, NHKV);

    rope_apply_kernel<<<(NB*NHQ *SB*64)/256, 256>>>(qbuf, NB*NHQ *SB*64);
    rope_apply_kernel<<<(NB*NHKV*SB*64)/256, 256>>>(kbuf, NB*NHKV*SB*64);

    // attention (tensor cores) -> fp16 [B,S,HqD]
    attn_wmma_kernel<<<dim3(16, NHQ, NB), 512, ATT_SMEM>>>(qbuf, kbuf, vbuf, aoh);

    // output projection -> d_out [B*S, HID]
    wgemm_nt<0><<<dim3(16, 32), 256, 65536>>>(aoh, woh, nullptr, outp, HID, NHQ*DH, 0);
}